// round 5
// baseline (speedup 1.0000x reference)
#include <cuda_runtime.h>
#include <cuda_bf16.h>
#include <cstdint>

namespace {
constexpr int NTOK = 256;
constexpr int DIM  = 1024;
}

// ---------------- scratch (static device globals, graph/alloc-safe) --------
__device__ float g_sim[3][NTOK * NTOK];   // 0: sim12, 1: sim11, 2: sim22
__device__ double g_loss;
__device__ unsigned long long g_pairs;
__device__ int g_selIsByte;

// ---------------- helpers ---------------------------------------------------
__device__ __forceinline__ uint32_t smem_u32(const void* p) {
    uint32_t a;
    asm("{ .reg .u64 t; cvta.to.shared.u64 t, %1; cvt.u32.u64 %0, t; }" : "=r"(a) : "l"(p));
    return a;
}
__device__ __forceinline__ void ldsm4(uint32_t* r, uint32_t addr) {
    asm volatile("ldmatrix.sync.aligned.m8n8.x4.shared.b16 {%0,%1,%2,%3}, [%4];"
                 : "=r"(r[0]), "=r"(r[1]), "=r"(r[2]), "=r"(r[3]) : "r"(addr));
}
__device__ __forceinline__ void mma_bf16(float* c, const uint32_t* a, const uint32_t* b) {
    asm volatile("mma.sync.aligned.m16n8k16.row.col.f32.bf16.bf16.f32 "
                 "{%0,%1,%2,%3}, {%4,%5,%6,%7}, {%8,%9}, {%0,%1,%2,%3};"
                 : "+f"(c[0]), "+f"(c[1]), "+f"(c[2]), "+f"(c[3])
                 : "r"(a[0]), "r"(a[1]), "r"(a[2]), "r"(a[3]), "r"(b[0]), "r"(b[1]));
}
// float4 -> (hi bf162 x2, lo bf162 x2)
__device__ __forceinline__ void split4(const float4 v, uint2& hi, uint2& lo) {
    __nv_bfloat16 h0 = __float2bfloat16_rn(v.x);
    __nv_bfloat16 h1 = __float2bfloat16_rn(v.y);
    __nv_bfloat16 h2 = __float2bfloat16_rn(v.z);
    __nv_bfloat16 h3 = __float2bfloat16_rn(v.w);
    __nv_bfloat162 hA(h0, h1), hB(h2, h3);
    __nv_bfloat162 lA(__float2bfloat16_rn(v.x - __bfloat162float(h0)),
                      __float2bfloat16_rn(v.y - __bfloat162float(h1)));
    __nv_bfloat162 lB(__float2bfloat16_rn(v.z - __bfloat162float(h2)),
                      __float2bfloat16_rn(v.w - __bfloat162float(h3)));
    hi = make_uint2(*(uint32_t*)&hA, *(uint32_t*)&hB);
    lo = make_uint2(*(uint32_t*)&lA, *(uint32_t*)&lB);
}

// ---------------------------------------------------------------------------
// Init: zero accumulators + sniff mask_sents dtype (bool bytes vs int32).
// ---------------------------------------------------------------------------
__global__ __launch_bounds__(256) void init_kernel(const unsigned char* __restrict__ s1,
                                                   const unsigned char* __restrict__ s2) {
    const int t = threadIdx.x;
    int v = 0;
    if ((t & 3) != 0) v = (int)s1[t] | (int)s2[t];
    const int any = __syncthreads_or(v);
    if (t == 0) {
        g_loss = 0.0;
        g_pairs = 0ull;
        g_selIsByte = (any != 0) ? 1 : 0;
    }
}

// ---------------------------------------------------------------------------
// Full-K tensor GEMM (mma.sync, plain compute_103-safe). No split-k, no
// partial buffers: each block owns a 32x64 output tile of one matrix term and
// loops K=1024 in 64-wide chunks, converting fp32 -> bf16 hi/lo during
// staging (fp32 and hi+lo bf16 have identical byte traffic, so the separate
// convert kernel is free to delete). acc = hiA*hiB + hiA*loB + loA*hiB.
// grid = 96: bz -> m = bz/32 (term), rt = (bz%32)>>2 (row/32), ct = bz&3 (col/64)
// 8 warps as 2x4: warp tile 16x16. SMEM stride 72 halves (144B) -> ldmatrix
// row addresses i*144 mod 128 = i*16: conflict-free.
// ---------------------------------------------------------------------------
__global__ __launch_bounds__(256) void gemm_mma_kernel(const float* __restrict__ f1,
                                                       const float* __restrict__ f2) {
    __shared__ __align__(16) __nv_bfloat16 sAh[32 * 72];
    __shared__ __align__(16) __nv_bfloat16 sAl[32 * 72];
    __shared__ __align__(16) __nv_bfloat16 sBh[64 * 72];
    __shared__ __align__(16) __nv_bfloat16 sBl[64 * 72];

    const int tid = threadIdx.x;
    const int lane = tid & 31;
    const int wid = tid >> 5;

    const int bz = blockIdx.x;
    const int m = bz >> 5;
    const int rem = bz & 31;
    const int rt = rem >> 2;
    const int ct = rem & 3;
    const int rbase = rt * 32;
    const int cbase = ct * 64;

    const float* __restrict__ A = (m == 2) ? f2 : f1;
    const float* __restrict__ B = (m == 1) ? f1 : f2;

    const uint32_t uAh = smem_u32(sAh);
    const uint32_t uAl = smem_u32(sAl);
    const uint32_t uBh = smem_u32(sBh);
    const uint32_t uBl = smem_u32(sBl);

    const int wr = wid >> 2;     // 0..1 (16-row group)
    const int wc = wid & 3;      // 0..3 (16-col group)

    // ldmatrix lane addressing (half offsets)
    const int arow = lane & 15;
    const int acol = (lane >> 4) << 3;
    const uint32_t aoff = (uint32_t)(((wr * 16 + arow) * 72 + acol) * 2);
    const int bi = lane & 7;
    const int bq = lane >> 3;
    const uint32_t boff = (uint32_t)(((wc * 16 + ((bq >> 1) << 3) + bi) * 72 + ((bq & 1) << 3)) * 2);

    float C[2][4];
#pragma unroll
    for (int nt = 0; nt < 2; nt++)
#pragma unroll
        for (int q = 0; q < 4; q++) C[nt][q] = 0.f;

    for (int chunk = 0; chunk < 16; chunk++) {
        const int kg = chunk * 64;
        __syncthreads();
        // Stage A: 32 rows x 64 floats = 512 uint4 (2 per thread)
#pragma unroll
        for (int it = 0; it < 2; it++) {
            const int v = tid + it * 256;
            const int r = v >> 4;
            const int q = v & 15;
            const float4 src = *(const float4*)&A[(rbase + r) * DIM + kg + q * 4];
            uint2 hi, lo;
            split4(src, hi, lo);
            *(uint2*)&sAh[r * 72 + q * 4] = hi;
            *(uint2*)&sAl[r * 72 + q * 4] = lo;
        }
        // Stage B: 64 rows x 64 floats = 1024 uint4 (4 per thread)
#pragma unroll
        for (int it = 0; it < 4; it++) {
            const int v = tid + it * 256;
            const int r = v >> 4;
            const int q = v & 15;
            const float4 src = *(const float4*)&B[(cbase + r) * DIM + kg + q * 4];
            uint2 hi, lo;
            split4(src, hi, lo);
            *(uint2*)&sBh[r * 72 + q * 4] = hi;
            *(uint2*)&sBl[r * 72 + q * 4] = lo;
        }
        __syncthreads();

#pragma unroll
        for (int kk = 0; kk < 4; kk++) {
            const uint32_t ka = aoff + kk * 32;  // kk*16 halves
            const uint32_t kb = boff + kk * 32;
            uint32_t ah[4], al[4], bh[4], bl[4];
            ldsm4(ah, uAh + ka);
            ldsm4(al, uAl + ka);
            ldsm4(bh, uBh + kb);
            ldsm4(bl, uBl + kb);
#pragma unroll
            for (int nt = 0; nt < 2; nt++) {
                mma_bf16(C[nt], ah, &bh[nt * 2]);
                mma_bf16(C[nt], ah, &bl[nt * 2]);
                mma_bf16(C[nt], al, &bh[nt * 2]);
            }
        }
    }

    // Epilogue: write g_sim tile directly (exclusive owner -> deterministic)
    float* __restrict__ dst = g_sim[m];
    const int erow = lane >> 2;
    const int ecol = (lane & 3) * 2;
#pragma unroll
    for (int nt = 0; nt < 2; nt++) {
        const int r0 = rbase + wr * 16 + erow;
        const int cc = cbase + wc * 16 + nt * 8 + ecol;
        *(float2*)&dst[r0 * NTOK + cc] = make_float2(C[nt][0], C[nt][1]);
        *(float2*)&dst[(r0 + 8) * NTOK + cc] = make_float2(C[nt][2], C[nt][3]);
    }
}

// ---------------------------------------------------------------------------
// Loss: one block per (term, row). Compacted pos/neg with sentinels padded to
// multiples of 32; templated NB keeps neg values register-resident; two
// interleaved product chains; one __logf per 32 pairs.
// ---------------------------------------------------------------------------
template <int NB>
__device__ __forceinline__ float row_loss(const float* __restrict__ sPos,
                                          const float* __restrict__ sNeg,
                                          int Ppad, int kl, int jg) {
    float nr[NB];
#pragma unroll
    for (int u = 0; u < NB; u++) nr[u] = sNeg[kl + u * 32];
    float relu = 0.f, lacc = 0.f;
    for (int j = jg; j < Ppad; j += 8) {
        const float p = sPos[j];
        float prodA = 1.f, prodB = 1.f;
#pragma unroll
        for (int u = 0; u < NB; u++) {
            const float x = nr[u] - p;
            relu += fmaxf(x, 0.f);
            const float e = __expf(-fabsf(x));
            if (u & 1) prodB = __fmaf_rn(prodB, e, prodB);
            else       prodA = __fmaf_rn(prodA, e, prodA);
        }
        lacc += __logf(prodA) + __logf(prodB);
    }
    return relu + lacc;
}

__global__ __launch_bounds__(256) void loss_kernel(const int* __restrict__ mc,
                                                   const int* __restrict__ m1,
                                                   const int* __restrict__ m2,
                                                   const void* __restrict__ s1p,
                                                   const void* __restrict__ s2p) {
    const int r = blockIdx.x;
    const int t = r >> 8;
    const int i = r & 255;

    const void* selP = (t == 0 || t == 2) ? s1p : s2p;
    int sel;
    if (g_selIsByte) sel = ((const unsigned char*)selP)[i];
    else             sel = ((const int*)selP)[i];
    if (!sel) return;

    __shared__ float sPos[256];
    __shared__ float sNeg[256];
    __shared__ int wPos[8];
    __shared__ float sRed[8];

    const int tid = threadIdx.x;
    const int lane = tid & 31;
    const int wid = tid >> 5;

    float v; int mk;
    if (t == 0)      { v = g_sim[0][i * 256 + tid]; mk = mc[i * 256 + tid]; }
    else if (t == 1) { v = g_sim[0][tid * 256 + i]; mk = mc[tid * 256 + i]; }
    else if (t == 2) { v = g_sim[1][i * 256 + tid]; mk = m1[i * 256 + tid]; }
    else             { v = g_sim[2][i * 256 + tid]; mk = m2[i * 256 + tid]; }

    const unsigned bp = __ballot_sync(0xffffffffu, mk != 0);
    if (lane == 0) wPos[wid] = __popc(bp);
    __syncthreads();

    int baseP = 0, P = 0;
#pragma unroll
    for (int w = 0; w < 8; w++) {
        const int c = wPos[w];
        if (w < wid) baseP += c;
        P += c;
    }
    const int N = 256 - P;
    const int baseN = wid * 32 - baseP;
    const unsigned lt = (1u << lane) - 1u;
    if (mk) sPos[baseP + __popc(bp & lt)] = v;
    else    sNeg[baseN + __popc(~bp & lt)] = v;
    __syncthreads();

    if (tid == 0)
        atomicAdd(&g_pairs, (unsigned long long)P * (unsigned long long)N);
    if (P == 0 || N == 0) return;

    const int Ppad = (P + 31) & ~31;
    const int Npad = (N + 31) & ~31;
    if (tid >= P && tid < Ppad) sPos[tid] = 1e30f;
    if (tid >= N && tid < Npad) sNeg[tid] = -1e30f;
    __syncthreads();

    const int kl = tid & 31;
    const int jg = tid >> 5;
    float total;
    switch (Npad >> 5) {
        case 1: total = row_loss<1>(sPos, sNeg, Ppad, kl, jg); break;
        case 2: total = row_loss<2>(sPos, sNeg, Ppad, kl, jg); break;
        case 3: total = row_loss<3>(sPos, sNeg, Ppad, kl, jg); break;
        case 4: total = row_loss<4>(sPos, sNeg, Ppad, kl, jg); break;
        case 5: total = row_loss<5>(sPos, sNeg, Ppad, kl, jg); break;
        case 6: total = row_loss<6>(sPos, sNeg, Ppad, kl, jg); break;
        case 7: total = row_loss<7>(sPos, sNeg, Ppad, kl, jg); break;
        default: total = row_loss<8>(sPos, sNeg, Ppad, kl, jg); break;
    }

#pragma unroll
    for (int o = 16; o; o >>= 1) total += __shfl_xor_sync(0xffffffffu, total, o);
    if (lane == 0) sRed[wid] = total;
    __syncthreads();
    if (tid == 0) {
        float bs = 0.f;
#pragma unroll
        for (int w = 0; w < 8; w++) bs += sRed[w];
        atomicAdd(&g_loss, (double)bs);
    }
}

__global__ void final_kernel(float* __restrict__ out) {
    const unsigned long long p = g_pairs;
    const double l = g_loss;
    out[0] = (float)((p > 0ull) ? (l / (double)p) : l);
}

// ---------------------------------------------------------------------------
// Inputs: 0 f1 f32[256,1024]  1 f2 f32[256,1024]  2 mask_cross i32[256,256]
//         3 mask1 i32[256,256] 4 mask2 i32[256,256] 5/6 mask_sents bool[256]
// ---------------------------------------------------------------------------
extern "C" void kernel_launch(void* const* d_in, const int* in_sizes, int n_in,
                              void* d_out, int out_size) {
    const float* f1 = (const float*)d_in[0];
    const float* f2 = (const float*)d_in[1];
    const int* mc = (const int*)d_in[2];
    const int* m1 = (const int*)d_in[3];
    const int* m2 = (const int*)d_in[4];
    const unsigned char* s1 = (const unsigned char*)d_in[5];
    const unsigned char* s2 = (const unsigned char*)d_in[6];

    init_kernel<<<1, 256>>>(s1, s2);
    gemm_mma_kernel<<<96, 256>>>(f1, f2);
    loss_kernel<<<1024, 256>>>(mc, m1, m2, (const void*)s1, (const void*)s2);
    final_kernel<<<1, 1>>>((float*)d_out);
}

// round 8
// speedup vs baseline: 1.1262x; 1.1262x over previous
#include <cuda_runtime.h>
#include <cuda_bf16.h>
#include <cstdint>

namespace {
constexpr int NTOK = 256;
constexpr int DIM  = 1024;
}

// ---------------- scratch (static device globals, graph/alloc-safe) --------
__device__ float g_part[24][NTOK * NTOK];     // split-k partials: z = m*8 + s
__device__ __nv_bfloat16 g_bf[4][NTOK * DIM]; // 0:hi1 1:lo1 2:hi2 3:lo2
__device__ double g_loss;                      // zero-init; reset by last loss block
__device__ unsigned long long g_pairs;         // idem
__device__ unsigned g_count;                   // idem
__device__ int g_selIsByte;

// ---------------- helpers ---------------------------------------------------
__device__ __forceinline__ uint32_t smem_u32(const void* p) {
    uint32_t a;
    asm("{ .reg .u64 t; cvta.to.shared.u64 t, %1; cvt.u32.u64 %0, t; }" : "=r"(a) : "l"(p));
    return a;
}
__device__ __forceinline__ void ldsm4(uint32_t* r, uint32_t addr) {
    asm volatile("ldmatrix.sync.aligned.m8n8.x4.shared.b16 {%0,%1,%2,%3}, [%4];"
                 : "=r"(r[0]), "=r"(r[1]), "=r"(r[2]), "=r"(r[3]) : "r"(addr));
}
__device__ __forceinline__ void mma_bf16(float* c, const uint32_t* a, const uint32_t* b) {
    asm volatile("mma.sync.aligned.m16n8k16.row.col.f32.bf16.bf16.f32 "
                 "{%0,%1,%2,%3}, {%4,%5,%6,%7}, {%8,%9}, {%0,%1,%2,%3};"
                 : "+f"(c[0]), "+f"(c[1]), "+f"(c[2]), "+f"(c[3])
                 : "r"(a[0]), "r"(a[1]), "r"(a[2]), "r"(a[3]), "r"(b[0]), "r"(b[1]));
}

// ---------------------------------------------------------------------------
// Convert fp32 features -> (hi, lo) bf16 pairs. Block 0 additionally sniffs
// whether mask_sents buffers are 1-byte bool or int32 (int32 {0,1} has all
// non-word-aligned bytes zero; a random bool vector ~surely doesn't).
// ---------------------------------------------------------------------------
__global__ __launch_bounds__(256) void convert_kernel(const float* __restrict__ f1,
                                                      const float* __restrict__ f2,
                                                      const unsigned char* __restrict__ s1,
                                                      const unsigned char* __restrict__ s2) {
    const int tid = threadIdx.x;
    if (blockIdx.x == 0) {
        int v = 0;
        if ((tid & 3) != 0) v = (int)s1[tid] | (int)s2[tid];
        const int any = __syncthreads_or(v);
        if (tid == 0) g_selIsByte = (any != 0) ? 1 : 0;
    }
    const int idx = blockIdx.x * 256 + tid;           // 0..131071
    const int sel = idx >> 16;                        // 0: f1, 1: f2
    const int off = (idx & 65535) * 4;
    const float4 v = *(const float4*)&((sel ? f2 : f1)[off]);
    __nv_bfloat16 h0 = __float2bfloat16_rn(v.x);
    __nv_bfloat16 h1 = __float2bfloat16_rn(v.y);
    __nv_bfloat16 h2 = __float2bfloat16_rn(v.z);
    __nv_bfloat16 h3 = __float2bfloat16_rn(v.w);
    __nv_bfloat162 hA(h0, h1), hB(h2, h3);
    __nv_bfloat162 lA(__float2bfloat16_rn(v.x - __bfloat162float(h0)),
                      __float2bfloat16_rn(v.y - __bfloat162float(h1)));
    __nv_bfloat162 lB(__float2bfloat16_rn(v.z - __bfloat162float(h2)),
                      __float2bfloat16_rn(v.w - __bfloat162float(h3)));
    __nv_bfloat16* hd = g_bf[sel * 2];
    __nv_bfloat16* ld = g_bf[sel * 2 + 1];
    *(uint2*)&hd[off] = make_uint2(*(uint32_t*)&hA, *(uint32_t*)&hB);
    *(uint2*)&ld[off] = make_uint2(*(uint32_t*)&lA, *(uint32_t*)&lB);
}

// ---------------------------------------------------------------------------
// Tensor GEMM (mma.sync, plain compute_103-safe). Block tile 128 rows x 64
// cols over one 128-wide k-split. grid 192: bz = ((m*8)+s)*8 + rt*4 + ct
// (m matrix term, s k-split, rt row/128, ct col/64). 8 warps as 4x2, warp
// tile 32x32. bf16 split acc = hiA*hiB + hiA*loB + loA*hiB. SMEM stride 72
// halves (144B) -> ldmatrix conflict-free. Partials to g_part[m*8+s]
// (exclusive tiles -> deterministic); the loss kernel sums the 8 splits.
// ---------------------------------------------------------------------------
__global__ __launch_bounds__(256) void gemm_mma_kernel() {
    __shared__ __align__(16) __nv_bfloat16 sAh[128 * 72];
    __shared__ __align__(16) __nv_bfloat16 sAl[128 * 72];
    __shared__ __align__(16) __nv_bfloat16 sBh[64 * 72];
    __shared__ __align__(16) __nv_bfloat16 sBl[64 * 72];

    const int tid = threadIdx.x;
    const int lane = tid & 31;
    const int wid = tid >> 5;

    const int bz = blockIdx.x;
    const int tile = bz & 7;
    const int rt = tile >> 2;
    const int ct = tile & 3;
    const int zz = bz >> 3;
    const int m = zz >> 3;
    const int s = zz & 7;
    const int rbase = rt * 128;
    const int cbase = ct * 64;
    const int k0 = s * 128;

    const __nv_bfloat16* __restrict__ Ah = g_bf[(m == 2) ? 2 : 0];
    const __nv_bfloat16* __restrict__ Al = g_bf[(m == 2) ? 3 : 1];
    const __nv_bfloat16* __restrict__ Bh = g_bf[(m == 1) ? 0 : 2];
    const __nv_bfloat16* __restrict__ Bl = g_bf[(m == 1) ? 1 : 3];

    const uint32_t uAh = smem_u32(sAh);
    const uint32_t uAl = smem_u32(sAl);
    const uint32_t uBh = smem_u32(sBh);
    const uint32_t uBl = smem_u32(sBl);

    const int wr = wid >> 1;     // 0..3: 32-row group
    const int wc = wid & 1;      // 0..1: 32-col group

    // ldmatrix lane addressing (byte offsets)
    const int arow = lane & 15;
    const int acol = (lane >> 4) << 3;
    const uint32_t aoff = (uint32_t)(((wr * 32 + arow) * 72 + acol) * 2);
    const int bi = lane & 7;
    const int bq = lane >> 3;
    const uint32_t boff = (uint32_t)(((wc * 32 + ((bq >> 1) << 3) + bi) * 72 + ((bq & 1) << 3)) * 2);

    float C[2][4][4];
#pragma unroll
    for (int mt = 0; mt < 2; mt++)
#pragma unroll
        for (int nt = 0; nt < 4; nt++)
#pragma unroll
            for (int q = 0; q < 4; q++) C[mt][nt][q] = 0.f;

#pragma unroll
    for (int chunk = 0; chunk < 2; chunk++) {
        const int kg = k0 + chunk * 64;
        __syncthreads();
        // Stage A: 128 rows x 64 halves = 1024 uint4 per buffer (4/thread)
#pragma unroll
        for (int it = 0; it < 4; it++) {
            const int v = tid + it * 256;
            const int r = v >> 3;
            const int q = v & 7;
            const int g = (rbase + r) * DIM + kg + q * 8;
            const int o = r * 72 + q * 8;
            *(uint4*)&sAh[o] = *(const uint4*)&Ah[g];
            *(uint4*)&sAl[o] = *(const uint4*)&Al[g];
        }
        // Stage B: 64 rows x 64 halves = 512 uint4 per buffer (2/thread)
#pragma unroll
        for (int it = 0; it < 2; it++) {
            const int v = tid + it * 256;
            const int r = v >> 3;
            const int q = v & 7;
            const int g = (cbase + r) * DIM + kg + q * 8;
            const int o = r * 72 + q * 8;
            *(uint4*)&sBh[o] = *(const uint4*)&Bh[g];
            *(uint4*)&sBl[o] = *(const uint4*)&Bl[g];
        }
        __syncthreads();

#pragma unroll
        for (int kk = 0; kk < 4; kk++) {
            const uint32_t ka = aoff + kk * 32;   // kk*16 halves
            const uint32_t kb = boff + kk * 32;
            uint32_t ah[2][4], al[2][4], bh[8], bl[8];
            ldsm4(ah[0], uAh + ka);
            ldsm4(ah[1], uAh + ka + 16 * 72 * 2);
            ldsm4(al[0], uAl + ka);
            ldsm4(al[1], uAl + ka + 16 * 72 * 2);
            ldsm4(bh,     uBh + kb);
            ldsm4(bh + 4, uBh + kb + 16 * 72 * 2);
            ldsm4(bl,     uBl + kb);
            ldsm4(bl + 4, uBl + kb + 16 * 72 * 2);
#pragma unroll
            for (int mt = 0; mt < 2; mt++)
#pragma unroll
                for (int nt = 0; nt < 4; nt++) {
                    mma_bf16(C[mt][nt], ah[mt], &bh[nt * 2]);
                    mma_bf16(C[mt][nt], ah[mt], &bl[nt * 2]);
                    mma_bf16(C[mt][nt], al[mt], &bh[nt * 2]);
                }
        }
    }

    // Epilogue: write split-k partials (exclusive tiles -> deterministic)
    float* __restrict__ dst = g_part[m * 8 + s];
    const int erow = lane >> 2;
    const int ecol = (lane & 3) * 2;
#pragma unroll
    for (int mt = 0; mt < 2; mt++)
#pragma unroll
        for (int nt = 0; nt < 4; nt++) {
            const int r0 = rbase + wr * 32 + mt * 16 + erow;
            const int cc = cbase + wc * 32 + nt * 8 + ecol;
            *(float2*)&dst[r0 * NTOK + cc] = make_float2(C[mt][nt][0], C[mt][nt][1]);
            *(float2*)&dst[(r0 + 8) * NTOK + cc] = make_float2(C[mt][nt][2], C[mt][nt][3]);
        }
}

// ---------------------------------------------------------------------------
// Loss (+ fused split-k reduce + fused final): one block per (term, row).
// Each thread sums the 8 L2-resident split-k partials while loading. After
// contributions, the LAST block (threadfence + counter) computes the output
// scalar and resets the accumulators for the next graph replay.
// ---------------------------------------------------------------------------
template <int NB>
__device__ __forceinline__ float row_loss(const float* __restrict__ sPos,
                                          const float* __restrict__ sNeg,
                                          int Ppad, int kl, int jg) {
    float nr[NB];
#pragma unroll
    for (int u = 0; u < NB; u++) nr[u] = sNeg[kl + u * 32];
    float relu = 0.f, lacc = 0.f;
    for (int j = jg; j < Ppad; j += 8) {
        const float p = sPos[j];
        float prodA = 1.f, prodB = 1.f;
#pragma unroll
        for (int u = 0; u < NB; u++) {
            const float x = nr[u] - p;
            relu += fmaxf(x, 0.f);
            const float e = __expf(-fabsf(x));
            if (u & 1) prodB = __fmaf_rn(prodB, e, prodB);
            else       prodA = __fmaf_rn(prodA, e, prodA);
        }
        lacc += __logf(prodA) + __logf(prodB);
    }
    return relu + lacc;
}

__global__ __launch_bounds__(256) void loss_kernel(const int* __restrict__ mc,
                                                   const int* __restrict__ m1,
                                                   const int* __restrict__ m2,
                                                   const void* __restrict__ s1p,
                                                   const void* __restrict__ s2p,
                                                   float* __restrict__ out) {
    const int r = blockIdx.x;
    const int t = r >> 8;
    const int i = r & 255;

    const void* selP = (t == 0 || t == 2) ? s1p : s2p;
    int sel;
    if (g_selIsByte) sel = ((const unsigned char*)selP)[i];
    else             sel = ((const int*)selP)[i];

    __shared__ float sPos[256];
    __shared__ float sNeg[256];
    __shared__ int wPos[8];
    __shared__ float sRed[8];

    const int tid = threadIdx.x;
    const int lane = tid & 31;
    const int wid = tid >> 5;

    if (sel) {  // uniform across block
        const int mIdx = (t <= 1) ? 0 : (t - 1);
        const int off = (t == 1) ? (tid * 256 + i) : (i * 256 + tid);
        const float* __restrict__ pb = g_part[mIdx * 8];
        float v = 0.f;
#pragma unroll
        for (int sp = 0; sp < 8; sp++) v += pb[sp * 65536 + off];

        int mk;
        if (t == 0)      mk = mc[i * 256 + tid];
        else if (t == 1) mk = mc[tid * 256 + i];
        else if (t == 2) mk = m1[i * 256 + tid];
        else             mk = m2[i * 256 + tid];

        const unsigned bp = __ballot_sync(0xffffffffu, mk != 0);
        if (lane == 0) wPos[wid] = __popc(bp);
        __syncthreads();

        int baseP = 0, P = 0;
#pragma unroll
        for (int w = 0; w < 8; w++) {
            const int c = wPos[w];
            if (w < wid) baseP += c;
            P += c;
        }
        const int N = 256 - P;
        const int baseN = wid * 32 - baseP;
        const unsigned lt = (1u << lane) - 1u;
        if (mk) sPos[baseP + __popc(bp & lt)] = v;
        else    sNeg[baseN + __popc(~bp & lt)] = v;
        __syncthreads();

        if (tid == 0)
            atomicAdd(&g_pairs, (unsigned long long)P * (unsigned long long)N);

        if (P != 0 && N != 0) {  // uniform
            const int Ppad = (P + 31) & ~31;
            const int Npad = (N + 31) & ~31;
            if (tid >= P && tid < Ppad) sPos[tid] = 1e30f;
            if (tid >= N && tid < Npad) sNeg[tid] = -1e30f;
            __syncthreads();

            const int kl = tid & 31;
            const int jg = tid >> 5;
            float total;
            switch (Npad >> 5) {
                case 1: total = row_loss<1>(sPos, sNeg, Ppad, kl, jg); break;
                case 2: total = row_loss<2>(sPos, sNeg, Ppad, kl, jg); break;
                case 3: total = row_loss<3>(sPos, sNeg, Ppad, kl, jg); break;
                case 4: total = row_loss<4>(sPos, sNeg, Ppad, kl, jg); break;
                case 5: total = row_loss<5>(sPos, sNeg, Ppad, kl, jg); break;
                case 6: total = row_loss<6>(sPos, sNeg, Ppad, kl, jg); break;
                case 7: total = row_loss<7>(sPos, sNeg, Ppad, kl, jg); break;
                default: total = row_loss<8>(sPos, sNeg, Ppad, kl, jg); break;
            }

#pragma unroll
            for (int o = 16; o; o >>= 1) total += __shfl_xor_sync(0xffffffffu, total, o);
            if (lane == 0) sRed[wid] = total;
            __syncthreads();
            if (tid == 0) {
                float bs = 0.f;
#pragma unroll
                for (int w = 0; w < 8; w++) bs += sRed[w];
                atomicAdd(&g_loss, (double)bs);
            }
        }
    }

    // Completion protocol: every block arrives; the last one finalizes.
    __threadfence();
    if (tid == 0) {
        const unsigned old = atomicAdd(&g_count, 1u);
        if (old == (unsigned)(gridDim.x - 1)) {
            const unsigned long long p = g_pairs;
            const double l = g_loss;
            out[0] = (float)((p > 0ull) ? (l / (double)p) : l);
            g_loss = 0.0;          // reset for next graph replay
            g_pairs = 0ull;
            g_count = 0u;
            __threadfence();
        }
    }
}

// ---------------------------------------------------------------------------
// Inputs: 0 f1 f32[256,1024]  1 f2 f32[256,1024]  2 mask_cross i32[256,256]
//         3 mask1 i32[256,256] 4 mask2 i32[256,256] 5/6 mask_sents bool[256]
// ---------------------------------------------------------------------------
extern "C" void kernel_launch(void* const* d_in, const int* in_sizes, int n_in,
                              void* d_out, int out_size) {
    const float* f1 = (const float*)d_in[0];
    const float* f2 = (const float*)d_in[1];
    const int* mc = (const int*)d_in[2];
    const int* m1 = (const int*)d_in[3];
    const int* m2 = (const int*)d_in[4];
    const unsigned char* s1 = (const unsigned char*)d_in[5];
    const unsigned char* s2 = (const unsigned char*)d_in[6];

    convert_kernel<<<512, 256>>>(f1, f2, s1, s2);
    gemm_mma_kernel<<<192, 256>>>();
    loss_kernel<<<1024, 256>>>(mc, m1, m2, (const void*)s1, (const void*)s2,
                               (float*)d_out);
}